// round 1
// baseline (speedup 1.0000x reference)
#include <cuda_runtime.h>

#define BATCH 4096
#define FEAT  4096

// per-row hinge values (scratch — no device allocation allowed in kernel_launch)
__device__ float g_row_hinge[BATCH];

__global__ void __launch_bounds__(256) row_dist_kernel(
    const float* __restrict__ out1,
    const float* __restrict__ out2,
    const float* __restrict__ out3)
{
    const int row = blockIdx.x;
    const size_t base = (size_t)row * FEAT;
    const float4* __restrict__ p1 = reinterpret_cast<const float4*>(out1 + base);
    const float4* __restrict__ p2 = reinterpret_cast<const float4*>(out2 + base);
    const float4* __restrict__ p3 = reinterpret_cast<const float4*>(out3 + base);

    float s13 = 0.0f;  // sum (o1-o3)^2
    float s12 = 0.0f;  // sum (o1-o2)^2

    // FEAT/4 = 1024 float4 per row; 256 threads -> 4 iterations each.
    #pragma unroll
    for (int it = 0; it < (FEAT / 4) / 256; ++it) {
        const int i = it * 256 + threadIdx.x;
        float4 a = p1[i];
        float4 b = p2[i];
        float4 c = p3[i];
        float d;
        d = a.x - c.x; s13 = fmaf(d, d, s13);
        d = a.y - c.y; s13 = fmaf(d, d, s13);
        d = a.z - c.z; s13 = fmaf(d, d, s13);
        d = a.w - c.w; s13 = fmaf(d, d, s13);
        d = a.x - b.x; s12 = fmaf(d, d, s12);
        d = a.y - b.y; s12 = fmaf(d, d, s12);
        d = a.z - b.z; s12 = fmaf(d, d, s12);
        d = a.w - b.w; s12 = fmaf(d, d, s12);
    }

    // warp reduction of both sums
    #pragma unroll
    for (int off = 16; off > 0; off >>= 1) {
        s13 += __shfl_xor_sync(0xFFFFFFFFu, s13, off);
        s12 += __shfl_xor_sync(0xFFFFFFFFu, s12, off);
    }

    __shared__ float sh13[8];
    __shared__ float sh12[8];
    const int lane = threadIdx.x & 31;
    const int wid  = threadIdx.x >> 5;
    if (lane == 0) { sh13[wid] = s13; sh12[wid] = s12; }
    __syncthreads();

    if (wid == 0) {
        s13 = (lane < 8) ? sh13[lane] : 0.0f;
        s12 = (lane < 8) ? sh12[lane] : 0.0f;
        #pragma unroll
        for (int off = 4; off > 0; off >>= 1) {
            s13 += __shfl_xor_sync(0xFFFFFFFFu, s13, off);
            s12 += __shfl_xor_sync(0xFFFFFFFFu, s12, off);
        }
        if (lane == 0) {
            float compare = 2.0f - sqrtf(s13) + sqrtf(s12);
            g_row_hinge[row] = fmaxf(0.0f, compare);
        }
    }
}

__global__ void __launch_bounds__(1024) final_reduce_kernel(float* __restrict__ out)
{
    float s = 0.0f;
    #pragma unroll
    for (int it = 0; it < BATCH / 1024; ++it)
        s += g_row_hinge[it * 1024 + threadIdx.x];

    #pragma unroll
    for (int off = 16; off > 0; off >>= 1)
        s += __shfl_xor_sync(0xFFFFFFFFu, s, off);

    __shared__ float sh[32];
    const int lane = threadIdx.x & 31;
    const int wid  = threadIdx.x >> 5;
    if (lane == 0) sh[wid] = s;
    __syncthreads();

    if (wid == 0) {
        s = (lane < 32) ? sh[lane] : 0.0f;
        #pragma unroll
        for (int off = 16; off > 0; off >>= 1)
            s += __shfl_xor_sync(0xFFFFFFFFu, s, off);
        if (lane == 0)
            out[0] = s * (float)BATCH;  // [B,B] broadcast -> scale by B
    }
}

extern "C" void kernel_launch(void* const* d_in, const int* in_sizes, int n_in,
                              void* d_out, int out_size)
{
    const float* out1 = (const float*)d_in[0];
    const float* out2 = (const float*)d_in[1];
    const float* out3 = (const float*)d_in[2];
    float* out = (float*)d_out;

    row_dist_kernel<<<BATCH, 256>>>(out1, out2, out3);
    final_reduce_kernel<<<1, 1024>>>(out);
}